// round 9
// baseline (speedup 1.0000x reference)
#include <cuda_runtime.h>
#include <cstdint>

// TVConv: per-pixel spatially-varying 3x3 depthwise conv, zero padding.
// x:           (B=8, C=96, H=128, W=128) fp32
// weight_maps: (1,   C=96, 3, 3, H, W)   fp32  (batch-invariant)
// out:         (B, C, H, W) fp32
//
// R7 (23.0us): 4px/thread, warp==row, register weights, prefetch-1,
// lb(256,3). MLP analysis says latency is covered; remaining waste is the
// end-of-kernel drain (1536 long blocks over 444 slots).
// R8: split the batch loop across 2 blocks (b 0-3 / 4-7) per row-group.
// Block duration halves -> drain tail halves. The paired block re-reads
// the same weight lines ~concurrently -> L2 hit, so DRAM weight traffic
// stays ~1x. Weights use default cache policy (not __ldcs) so the pair
// reuse survives; out keeps __stcs (write-only, no reuse).

namespace {
constexpr int B = 8;
constexpr int BSPLIT = 2;            // blocks sharing one row-group
constexpr int BPB = B / BSPLIT;      // batches per block = 4
constexpr int C = 96;
constexpr int H = 128;
constexpr int W = 128;
constexpr int HW = H * W;
constexpr int THREADS = 256;
constexpr int ROWGROUP_BLOCKS = C * H * (W / 4) / THREADS;  // 1536
constexpr int NBLOCKS = ROWGROUP_BLOCKS * BSPLIT;           // 3072
}

__device__ __forceinline__ float4 ldg4(const float* p) {
    return *reinterpret_cast<const float4*>(p);
}

__device__ __forceinline__ void accum_row(
    float4 r, float4 k0, float4 k1, float4 k2,
    float& a0, float& a1, float& a2, float& a3, int lane)
{
    float left  = __shfl_up_sync(0xffffffffu,  r.w, 1);
    float right = __shfl_down_sync(0xffffffffu, r.x, 1);
    if (lane == 0)  left  = 0.f;   // w = -1  -> zero pad
    if (lane == 31) right = 0.f;   // w = 128 -> zero pad
    a0 = fmaf(k0.x, left, fmaf(k1.x, r.x, fmaf(k2.x, r.y, a0)));
    a1 = fmaf(k0.y, r.x,  fmaf(k1.y, r.y, fmaf(k2.y, r.z, a1)));
    a2 = fmaf(k0.z, r.y,  fmaf(k1.z, r.z, fmaf(k2.z, r.w, a2)));
    a3 = fmaf(k0.w, r.z,  fmaf(k1.w, r.w, fmaf(k2.w, right, a3)));
}

__global__ __launch_bounds__(THREADS, 3) void tvconv_kernel(
    const float* __restrict__ x,
    const float* __restrict__ wm,
    float* __restrict__ out)
{
    int rg     = blockIdx.x >> 1;          // row-group block
    int bstart = (blockIdx.x & 1) * BPB;   // 0 or 4

    int idx  = rg * THREADS + threadIdx.x;
    int lane = threadIdx.x & 31;           // == w4 (W/4 == 32)
    int t    = idx >> 5;
    int h    = t % H;
    int c    = t / H;
    int w0   = lane * 4;

    // ---- 9 weight taps, register-resident (default cache policy: the
    //      paired block re-reads these lines shortly -> L2 hit) ----
    const float* wbase = wm + (size_t)c * 9 * HW + (size_t)h * W + w0;
    float4 wt[9];
#pragma unroll
    for (int k = 0; k < 9; k++)
        wt[k] = ldg4(wbase + (size_t)k * HW);

    const size_t chw = (size_t)c * HW + (size_t)h * W + w0;
    const bool has_up = (h > 0), has_dn = (h < H - 1);
    const float4 z4 = make_float4(0.f, 0.f, 0.f, 0.f);

    // prime first batch of this block's half
    const float* xp = x + (size_t)bstart * C * HW + chw;
    float4 c1 = ldg4(xp);
    float4 c0 = has_up ? ldg4(xp - W) : z4;
    float4 c2 = has_dn ? ldg4(xp + W) : z4;

#pragma unroll
    for (int bi = 0; bi < BPB; bi++) {
        int b = bstart + bi;
        float4 n0 = z4, n1 = z4, n2 = z4;
        if (bi + 1 < BPB) {            // prefetch next batch's 3 rows
            const float* xn = x + (size_t)(b + 1) * C * HW + chw;
            n1 = ldg4(xn);
            n0 = has_up ? ldg4(xn - W) : z4;
            n2 = has_dn ? ldg4(xn + W) : z4;
        }

        float a0 = 0.f, a1 = 0.f, a2 = 0.f, a3 = 0.f;
        accum_row(c0, wt[0], wt[1], wt[2], a0, a1, a2, a3, lane);
        accum_row(c1, wt[3], wt[4], wt[5], a0, a1, a2, a3, lane);
        accum_row(c2, wt[6], wt[7], wt[8], a0, a1, a2, a3, lane);

        __stcs(reinterpret_cast<float4*>(out + (size_t)b * C * HW + chw),
               make_float4(a0, a1, a2, a3));

        c0 = n0; c1 = n1; c2 = n2;
    }
}

extern "C" void kernel_launch(void* const* d_in, const int* in_sizes, int n_in,
                              void* d_out, int out_size)
{
    const float* x  = (const float*)d_in[0];
    const float* wm = (const float*)d_in[1];
    float* out      = (float*)d_out;

    tvconv_kernel<<<NBLOCKS, THREADS>>>(x, wm, out);
}

// round 11
// speedup vs baseline: 1.2692x; 1.2692x over previous
#include <cuda_runtime.h>
#include <cstdint>

// TVConv: per-pixel spatially-varying 3x3 depthwise conv, zero padding.
// x:           (B=8, C=96, H=128, W=128) fp32
// weight_maps: (1,   C=96, 3, 3, H, W)   fp32  (batch-invariant)
// out:         (B, C, H, W) fp32
//
// R8 lesson: batch-splitting doubles weight traffic; tail is not the
// limiter. R9 = R7 (4px/thread, warp==row, register weights, lb(256,3),
// __ldcs weights / __stcs out) + DISTANCE-2 software pipeline: loads for
// batch b+2 are in flight while batch b computes (~720cyc cover vs
// ~600cyc DRAM latency; R7's distance-1 only covered ~360cyc).
// 32-bit offset arithmetic keeps regs inside the 85-reg lb(256,3) budget.

namespace {
constexpr int B = 8;
constexpr int C = 96;
constexpr int H = 128;
constexpr int W = 128;
constexpr int HW = H * W;
constexpr unsigned CHW = (unsigned)C * HW;        // x/out batch stride
constexpr int THREADS = 256;
constexpr int NBLOCKS = C * H * (W / 4) / THREADS;  // 1536
}

__device__ __forceinline__ float4 ldg4(const float* p) {
    return *reinterpret_cast<const float4*>(p);
}

__device__ __forceinline__ void accum_row(
    float4 r, float4 k0, float4 k1, float4 k2,
    float& a0, float& a1, float& a2, float& a3, int lane)
{
    float left  = __shfl_up_sync(0xffffffffu,  r.w, 1);
    float right = __shfl_down_sync(0xffffffffu, r.x, 1);
    if (lane == 0)  left  = 0.f;   // w = -1  -> zero pad
    if (lane == 31) right = 0.f;   // w = 128 -> zero pad
    a0 = fmaf(k0.x, left, fmaf(k1.x, r.x, fmaf(k2.x, r.y, a0)));
    a1 = fmaf(k0.y, r.x,  fmaf(k1.y, r.y, fmaf(k2.y, r.z, a1)));
    a2 = fmaf(k0.z, r.y,  fmaf(k1.z, r.z, fmaf(k2.z, r.w, a2)));
    a3 = fmaf(k0.w, r.z,  fmaf(k1.w, r.w, fmaf(k2.w, right, a3)));
}

__global__ __launch_bounds__(THREADS, 3) void tvconv_kernel(
    const float* __restrict__ x,
    const float* __restrict__ wm,
    float* __restrict__ out)
{
    int idx  = blockIdx.x * THREADS + threadIdx.x;
    int lane = threadIdx.x & 31;       // == w4 (W/4 == 32)
    int t    = idx >> 5;
    int h    = t % H;
    int c    = t / H;
    int w0   = lane * 4;

    // ---- 9 weight taps, register-resident, streaming (read-once) ----
    const float* wbase = wm + (unsigned)c * 9u * HW + (unsigned)h * W + w0;
    float4 wt[9];
#pragma unroll
    for (int k = 0; k < 9; k++)
        wt[k] = __ldcs(reinterpret_cast<const float4*>(wbase + (unsigned)k * HW));

    const unsigned chw = (unsigned)c * HW + (unsigned)h * W + w0;
    const bool has_up = (h > 0), has_dn = (h < H - 1);
    const float4 z4 = make_float4(0.f, 0.f, 0.f, 0.f);

    // ---- distance-2 pipeline: bu[b&1] holds batch b's 3 rows ----
    float4 bu[2][3];
    {
        const float* x0 = x + chw;                 // batch 0
        bu[0][1] = ldg4(x0);
        bu[0][0] = has_up ? ldg4(x0 - W) : z4;
        bu[0][2] = has_dn ? ldg4(x0 + W) : z4;
        const float* x1 = x + CHW + chw;           // batch 1
        bu[1][1] = ldg4(x1);
        bu[1][0] = has_up ? ldg4(x1 - W) : z4;
        bu[1][2] = has_dn ? ldg4(x1 + W) : z4;
    }

#pragma unroll
    for (int b = 0; b < B; b++) {
        const int s = b & 1;

        // issue batch b+2's loads FIRST (into temps; consumed two iters on)
        float4 p0 = z4, p1 = z4, p2 = z4;
        if (b + 2 < B) {
            const float* xn = x + (unsigned)(b + 2) * CHW + chw;
            p1 = ldg4(xn);
            p0 = has_up ? ldg4(xn - W) : z4;
            p2 = has_dn ? ldg4(xn + W) : z4;
        }

        float a0 = 0.f, a1 = 0.f, a2 = 0.f, a3 = 0.f;
        accum_row(bu[s][0], wt[0], wt[1], wt[2], a0, a1, a2, a3, lane);
        accum_row(bu[s][1], wt[3], wt[4], wt[5], a0, a1, a2, a3, lane);
        accum_row(bu[s][2], wt[6], wt[7], wt[8], a0, a1, a2, a3, lane);

        __stcs(reinterpret_cast<float4*>(out + (unsigned)b * CHW + chw),
               make_float4(a0, a1, a2, a3));

        bu[s][0] = p0; bu[s][1] = p1; bu[s][2] = p2;
    }
}

extern "C" void kernel_launch(void* const* d_in, const int* in_sizes, int n_in,
                              void* d_out, int out_size)
{
    const float* x  = (const float*)d_in[0];
    const float* wm = (const float*)d_in[1];
    float* out      = (float*)d_out;

    tvconv_kernel<<<NBLOCKS, THREADS>>>(x, wm, out);
}